// round 15
// baseline (speedup 1.0000x reference)
#include <cuda_runtime.h>
#include <cstdint>

// LSTM B=4096 T=256 I=8 H=32 O=1.
// GATE-SPLIT design: CTA = 128 thr = 4 warps = 4 batch sequences; warp g owns
// gate g (i,f,g,o). lane j = hidden unit j.
//  - Weights per warp: 16 u64 natural k-pairs of W_hh row (g*32+j) + 4 u64 of
//    W_ih -> ~40 weight regs; __launch_bounds__(128,7) -> 7 CTAs/SM resident,
//    grid 1024 = 7*148 exactly (no waves, no imbalance), 7 warps/SMSP.
//  - f32x2 pairs adjacent k: fma2({h_2m,h_2m+1},{w_2m,w_2m+1}) -> horizontal
//    add finalizes z. h kept as plain floats in smem (broadcast LDS.128 reads).
//  - Per step: each warp computes FULL z_g for 4 batches, publishes to smem,
//    bar; warp g does activations for batch g only (MUFU 4/warp), writes h, bar.
//  - tanh.approx; sigmoid 0.5 scale folded into weights/bias of gates i,f,o.

#define B_TOT 4096
#define T_TOT 256
#define I_SZ 8
#define CHUNK 16

typedef unsigned long long u64;

__device__ __forceinline__ u64 pack2(float a, float b) {
    u64 r; asm("mov.b64 %0,{%1,%2};" : "=l"(r) : "f"(a), "f"(b)); return r;
}
__device__ __forceinline__ void unpack2(u64 v, float& a, float& b) {
    asm("mov.b64 {%0,%1},%2;" : "=f"(a), "=f"(b) : "l"(v));
}
__device__ __forceinline__ u64 fma2(u64 a, u64 b, u64 c) {
    u64 d; asm("fma.rn.f32x2 %0,%1,%2,%3;" : "=l"(d) : "l"(a), "l"(b), "l"(c)); return d;
}
__device__ __forceinline__ float tanhap(float x) {
    float y; asm("tanh.approx.f32 %0,%1;" : "=f"(y) : "f"(x)); return y;
}
// i,f,o z pre-scaled by 0.5: sigmoid(z) = 0.5*tanh(z/2) + 0.5
__device__ __forceinline__ float sig_h(float zhalf) {
    return fmaf(0.5f, tanhap(zhalf), 0.5f);
}

__global__ void __launch_bounds__(128, 7)
lstm_kernel(const float* __restrict__ x,
            const float* __restrict__ W_ih,
            const float* __restrict__ W_hh,
            const float* __restrict__ b_ih,
            const float* __restrict__ b_hh,
            const float* __restrict__ W_out,
            const float* __restrict__ b_out,
            float* __restrict__ out)
{
    __shared__ __align__(16) float h_sm[4 * 32];            // [b][j]
    __shared__ __align__(16) float z_sm[4 * 4 * 32];        // [gate][b][j]
    __shared__ __align__(16) u64  x_sm[CHUNK * 4 * 4];      // [t][b][ipair]

    const int lane = threadIdx.x & 31;
    const int g    = threadIdx.x >> 5;          // this warp's gate

    const float scale = (g == 2) ? 1.0f : 0.5f; // fold sigmoid half-scale

    // ---- W_hh row (g*32+lane) -> 16 natural k-pair registers ----
    u64 wk[16];
    {
        const float* wr = W_hh + (g * 32 + lane) * 32;
#pragma unroll
        for (int m = 0; m < 8; ++m) {
            const float4 v = *(const float4*)(wr + m * 4);
            wk[m * 2 + 0] = pack2(scale * v.x, scale * v.y);
            wk[m * 2 + 1] = pack2(scale * v.z, scale * v.w);
        }
    }
    // ---- W_ih row -> 4 natural i-pair registers ----
    u64 wx[4];
    {
        const float* wr = W_ih + (g * 32 + lane) * I_SZ;
#pragma unroll
        for (int p = 0; p < 2; ++p) {
            const float4 v = *(const float4*)(wr + p * 4);
            wx[p * 2 + 0] = pack2(scale * v.x, scale * v.y);
            wx[p * 2 + 1] = pack2(scale * v.z, scale * v.w);
        }
    }
    const u64 bacc = pack2(scale * (b_ih[g * 32 + lane] + b_hh[g * 32 + lane]), 0.0f);

    h_sm[g * 32 + lane] = 0.0f;      // zero initial h (warp g -> batch g row)
    float c = 0.0f, hmy = 0.0f;

    // warp g stages x for batch g
    const float* xb = x + ((size_t)blockIdx.x * 4 + g) * T_TOT * I_SZ;
    const int t_ = lane >> 1;            // 0..15
    const int i0 = (lane & 1) * 4;       // 0 or 4

#pragma unroll 1
    for (int tc = 0; tc < T_TOT / CHUNK; ++tc) {
        __syncthreads();    // h init visible / prior chunk x reads complete
        {
            const float4 v = *(const float4*)(xb + (size_t)(tc * CHUNK + t_) * I_SZ + i0);
            *(ulonglong2*)(x_sm + (t_ * 4 + g) * 4 + (i0 >> 1)) =
                make_ulonglong2(pack2(v.x, v.y), pack2(v.z, v.w));
        }
        __syncthreads();

#pragma unroll 1
        for (int s = 0; s < CHUNK; ++s) {
            u64 a0 = bacc, a1 = bacc, a2 = bacc, a3 = bacc;

            // ---- input projection (broadcast x pairs, register weights) ----
            {
                const u64* xr = x_sm + s * 16;
                const ulonglong2 q0 = *(const ulonglong2*)(xr + 0);
                const ulonglong2 q1 = *(const ulonglong2*)(xr + 2);
                const ulonglong2 q2 = *(const ulonglong2*)(xr + 4);
                const ulonglong2 q3 = *(const ulonglong2*)(xr + 6);
                const ulonglong2 q4 = *(const ulonglong2*)(xr + 8);
                const ulonglong2 q5 = *(const ulonglong2*)(xr + 10);
                const ulonglong2 q6 = *(const ulonglong2*)(xr + 12);
                const ulonglong2 q7 = *(const ulonglong2*)(xr + 14);
                a0 = fma2(q0.x, wx[0], a0); a0 = fma2(q0.y, wx[1], a0);
                a0 = fma2(q1.x, wx[2], a0); a0 = fma2(q1.y, wx[3], a0);
                a1 = fma2(q2.x, wx[0], a1); a1 = fma2(q2.y, wx[1], a1);
                a1 = fma2(q3.x, wx[2], a1); a1 = fma2(q3.y, wx[3], a1);
                a2 = fma2(q4.x, wx[0], a2); a2 = fma2(q4.y, wx[1], a2);
                a2 = fma2(q5.x, wx[2], a2); a2 = fma2(q5.y, wx[3], a2);
                a3 = fma2(q6.x, wx[0], a3); a3 = fma2(q6.y, wx[1], a3);
                a3 = fma2(q7.x, wx[2], a3); a3 = fma2(q7.y, wx[3], a3);
            }

            // ---- recurrent: broadcast h pairs, register k-pair weights ----
#pragma unroll
            for (int m = 0; m < 8; ++m) {
                const ulonglong2 hb0 = *(const ulonglong2*)(h_sm + 0 * 32 + m * 4);
                const ulonglong2 hb1 = *(const ulonglong2*)(h_sm + 1 * 32 + m * 4);
                const ulonglong2 hb2 = *(const ulonglong2*)(h_sm + 2 * 32 + m * 4);
                const ulonglong2 hb3 = *(const ulonglong2*)(h_sm + 3 * 32 + m * 4);
                const u64 w0 = wk[2 * m], w1 = wk[2 * m + 1];
                a0 = fma2(hb0.x, w0, a0); a0 = fma2(hb0.y, w1, a0);
                a1 = fma2(hb1.x, w0, a1); a1 = fma2(hb1.y, w1, a1);
                a2 = fma2(hb2.x, w0, a2); a2 = fma2(hb2.y, w1, a2);
                a3 = fma2(hb3.x, w0, a3); a3 = fma2(hb3.y, w1, a3);
            }

            // ---- finalize z_g (horizontal add) and publish ----
            float lo, hi;
            unpack2(a0, lo, hi); z_sm[(g * 4 + 0) * 32 + lane] = lo + hi;
            unpack2(a1, lo, hi); z_sm[(g * 4 + 1) * 32 + lane] = lo + hi;
            unpack2(a2, lo, hi); z_sm[(g * 4 + 2) * 32 + lane] = lo + hi;
            unpack2(a3, lo, hi); z_sm[(g * 4 + 3) * 32 + lane] = lo + hi;
            __syncthreads();

            // ---- activation for batch g only ----
            const float zi = z_sm[(0 * 4 + g) * 32 + lane];
            const float zf = z_sm[(1 * 4 + g) * 32 + lane];
            const float zg = z_sm[(2 * 4 + g) * 32 + lane];
            const float zo = z_sm[(3 * 4 + g) * 32 + lane];
            c   = fmaf(sig_h(zf), c, sig_h(zi) * tanhap(zg));
            hmy = sig_h(zo) * tanhap(c);
            h_sm[g * 32 + lane] = hmy;
            __syncthreads();
        }
    }

    // ---- output head: warp g reduces batch g ----
    float v = hmy * W_out[lane];
#pragma unroll
    for (int off = 16; off; off >>= 1)
        v += __shfl_xor_sync(0xffffffffu, v, off);
    if (lane == 0)
        out[blockIdx.x * 4 + g] = v + b_out[0];
}

extern "C" void kernel_launch(void* const* d_in, const int* in_sizes, int n_in,
                              void* d_out, int out_size)
{
    const float* x     = (const float*)d_in[0];
    const float* W_ih  = (const float*)d_in[1];
    const float* W_hh  = (const float*)d_in[2];
    const float* b_ih  = (const float*)d_in[3];
    const float* b_hh  = (const float*)d_in[4];
    const float* W_out = (const float*)d_in[5];
    const float* b_out = (const float*)d_in[6];
    float* out = (float*)d_out;

    lstm_kernel<<<B_TOT / 4, 128>>>(x, W_ih, W_hh, b_ih, b_hh, W_out, b_out, out);
}

// round 16
// speedup vs baseline: 1.1830x; 1.1830x over previous
#include <cuda_runtime.h>
#include <cstdint>

// LSTM B=4096 T=256 I=8 H=32 O=1.
// Dual-group in-warp software pipeline on the R12 structure:
//  - CTA = 32 thr = 1 warp = 8 sequences in two independent groups A,B (4+4).
//  - lane j = hidden unit j. f32x2 lanes are GATE pairs {z_i,z_f},{z_g,z_o}.
//  - W_hh in regs as NATURAL gate pairs (128 regs) SHARED by both groups.
//  - W_ih gate pairs per-lane in smem. h and x PRE-DUPLICATED ({v,v} u64) in
//    per-group smem buffers; all hot LDS are broadcasts.
//  - Per step: matvec(A); matvec(B); act(A); act(B); stores; one syncwarp.
//    The two groups' chains interleave statically -> the activation/sync tail
//    of one group is filled by the other group's FMA stream.
//  - tanh.approx; sigmoid 0.5 scale folded into i,f,o weights/biases.
// Grid = 512 (B/8).

#define B_TOT 4096
#define T_TOT 256
#define I_SZ 8
#define CHUNK 16
#define XROW 9          // padded row (u64-pair units) per t: 8 i + 1 pad

typedef unsigned long long u64;

__device__ __forceinline__ u64 pack2(float a, float b) {
    u64 r; asm("mov.b64 %0,{%1,%2};" : "=l"(r) : "f"(a), "f"(b)); return r;
}
__device__ __forceinline__ void unpack2(u64 v, float& a, float& b) {
    asm("mov.b64 {%0,%1},%2;" : "=f"(a), "=f"(b) : "l"(v));
}
__device__ __forceinline__ u64 fma2(u64 a, u64 b, u64 c) {
    u64 d; asm("fma.rn.f32x2 %0,%1,%2,%3;" : "=l"(d) : "l"(a), "l"(b), "l"(c)); return d;
}
__device__ __forceinline__ float tanhap(float x) {
    float y; asm("tanh.approx.f32 %0,%1;" : "=f"(y) : "f"(x)); return y;
}
// i,f,o accumulators pre-scaled by 0.5: sigmoid(z)=0.5*tanh(z/2)+0.5
__device__ __forceinline__ float sig_h(float zhalf) {
    return fmaf(0.5f, tanhap(zhalf), 0.5f);
}

__global__ void __launch_bounds__(32)
lstm_kernel(const float* __restrict__ x,
            const float* __restrict__ W_ih,
            const float* __restrict__ W_hh,
            const float* __restrict__ b_ih,
            const float* __restrict__ b_hh,
            const float* __restrict__ W_out,
            const float* __restrict__ b_out,
            float* __restrict__ out)
{
    // per-CTA shared; u64 entries are {v,v} duplicated pairs
    __shared__ __align__(16) ulonglong2 wi_sm[I_SZ * 32];       // [i][j] {wif},{wgo}
    __shared__ __align__(16) u64 xbuf[2][2][CHUNK * XROW * 2];  // [grp][b01/b23]
    __shared__ __align__(16) u64 hbuf[2][2][2 * 32 * 2];        // [grp][b01/b23][cur][k][pair]

    const int lane = threadIdx.x & 31;

    // ---- W_hh rows -> registers as natural gate pairs (i,f,o x0.5) ----
    u64 wif[32], wgo[32];
    {
        const float* ri = W_hh + (0 * 32 + lane) * 32;
        const float* rf = W_hh + (1 * 32 + lane) * 32;
        const float* rg = W_hh + (2 * 32 + lane) * 32;
        const float* ro = W_hh + (3 * 32 + lane) * 32;
#pragma unroll
        for (int kk = 0; kk < 8; ++kk) {
            const float4 ai = *(const float4*)(ri + kk * 4);
            const float4 af = *(const float4*)(rf + kk * 4);
            const float4 ag = *(const float4*)(rg + kk * 4);
            const float4 ao = *(const float4*)(ro + kk * 4);
            wif[kk * 4 + 0] = pack2(0.5f * ai.x, 0.5f * af.x);
            wif[kk * 4 + 1] = pack2(0.5f * ai.y, 0.5f * af.y);
            wif[kk * 4 + 2] = pack2(0.5f * ai.z, 0.5f * af.z);
            wif[kk * 4 + 3] = pack2(0.5f * ai.w, 0.5f * af.w);
            wgo[kk * 4 + 0] = pack2(ag.x, 0.5f * ao.x);
            wgo[kk * 4 + 1] = pack2(ag.y, 0.5f * ao.y);
            wgo[kk * 4 + 2] = pack2(ag.z, 0.5f * ao.z);
            wgo[kk * 4 + 3] = pack2(ag.w, 0.5f * ao.w);
        }
    }

    // ---- W_ih gate pairs into smem (per-lane) ----
#pragma unroll
    for (int i = 0; i < I_SZ; ++i) {
        const float a = 0.5f * W_ih[(0 * 32 + lane) * I_SZ + i];
        const float b = 0.5f * W_ih[(1 * 32 + lane) * I_SZ + i];
        const float c =        W_ih[(2 * 32 + lane) * I_SZ + i];
        const float d = 0.5f * W_ih[(3 * 32 + lane) * I_SZ + i];
        wi_sm[i * 32 + lane] = make_ulonglong2(pack2(a, b), pack2(c, d));
    }

    // ---- zero h buffers ----
#pragma unroll
    for (int q = 0; q < 8; ++q) {
        hbuf[0][q & 1][(q >> 1) * 32 + lane] = 0ull;
        hbuf[1][q & 1][(q >> 1) * 32 + lane] = 0ull;
    }

    // ---- biases (gate pairs, i/f/o pre-scaled) ----
    const float bi_ = 0.5f * (b_ih[0 * 32 + lane] + b_hh[0 * 32 + lane]);
    const float bf_ = 0.5f * (b_ih[1 * 32 + lane] + b_hh[1 * 32 + lane]);
    const float bg_ =         b_ih[2 * 32 + lane] + b_hh[2 * 32 + lane];
    const float bo_ = 0.5f * (b_ih[3 * 32 + lane] + b_hh[3 * 32 + lane]);
    const u64 bif = pack2(bi_, bf_);
    const u64 bgo = pack2(bg_, bo_);

    float cs[8], hs[8];
#pragma unroll
    for (int b = 0; b < 8; ++b) { cs[b] = 0.f; hs[b] = 0.f; }

    int cur = 0;
    const float* xw = x + (size_t)blockIdx.x * 8 * T_TOT * I_SZ;
    const int t_ = lane >> 1;
    const int i0 = (lane & 1) * 4;

    __syncwarp();

#pragma unroll 1
    for (int tc = 0; tc < T_TOT / CHUNK; ++tc) {
        // ---- stage x chunks for both groups, pre-duplicated {x,x} ----
#pragma unroll
        for (int q = 0; q < 8; ++q) {          // q = grp*4 + b
            const int grp = q >> 2, b = q & 3;
            const float4 v = *(const float4*)(xw
                + ((size_t)q * T_TOT + tc * CHUNK + t_) * I_SZ + i0);
            u64* dst = xbuf[grp][b >> 1];
            const int p = b & 1;
            dst[(t_ * XROW + i0 + 0) * 2 + p] = pack2(v.x, v.x);
            dst[(t_ * XROW + i0 + 1) * 2 + p] = pack2(v.y, v.y);
            dst[(t_ * XROW + i0 + 2) * 2 + p] = pack2(v.z, v.z);
            dst[(t_ * XROW + i0 + 3) * 2 + p] = pack2(v.w, v.w);
        }
        __syncwarp();

#pragma unroll 1
        for (int s = 0; s < CHUNK; ++s) {
            u64 zif[2][4], zgo[2][4];

            // ---- matvec for both groups (single basic block: ptxas
            //      interleaves the two independent streams) ----
#pragma unroll
            for (int grp = 0; grp < 2; ++grp) {
                const u64* xA = xbuf[grp][0];
                const u64* xB = xbuf[grp][1];
                const u64* hra = hbuf[grp][0] + cur * 64;
                const u64* hrb = hbuf[grp][1] + cur * 64;

                u64 a0 = bif, a1 = bif, a2 = bif, a3 = bif;
                u64 g0 = bgo, g1 = bgo, g2 = bgo, g3 = bgo;

#pragma unroll
                for (int i = 0; i < I_SZ; ++i) {
                    const ulonglong2 x01 = *(const ulonglong2*)(xA + (s * XROW + i) * 2);
                    const ulonglong2 x23 = *(const ulonglong2*)(xB + (s * XROW + i) * 2);
                    const ulonglong2 wv  = wi_sm[i * 32 + lane];
                    a0 = fma2(x01.x, wv.x, a0); g0 = fma2(x01.x, wv.y, g0);
                    a1 = fma2(x01.y, wv.x, a1); g1 = fma2(x01.y, wv.y, g1);
                    a2 = fma2(x23.x, wv.x, a2); g2 = fma2(x23.x, wv.y, g2);
                    a3 = fma2(x23.y, wv.x, a3); g3 = fma2(x23.y, wv.y, g3);
                }
#pragma unroll
                for (int k = 0; k < 32; ++k) {
                    const ulonglong2 h01 = *(const ulonglong2*)(hra + k * 2);
                    const ulonglong2 h23 = *(const ulonglong2*)(hrb + k * 2);
                    a0 = fma2(h01.x, wif[k], a0); g0 = fma2(h01.x, wgo[k], g0);
                    a1 = fma2(h01.y, wif[k], a1); g1 = fma2(h01.y, wgo[k], g1);
                    a2 = fma2(h23.x, wif[k], a2); g2 = fma2(h23.x, wgo[k], g2);
                    a3 = fma2(h23.y, wif[k], a3); g3 = fma2(h23.y, wgo[k], g3);
                }
                zif[grp][0] = a0; zif[grp][1] = a1; zif[grp][2] = a2; zif[grp][3] = a3;
                zgo[grp][0] = g0; zgo[grp][1] = g1; zgo[grp][2] = g2; zgo[grp][3] = g3;
            }

            // ---- activations + state update, both groups (8 indep chains) ----
            const int nxt = cur ^ 1;
#pragma unroll
            for (int grp = 0; grp < 2; ++grp) {
#pragma unroll
                for (int b = 0; b < 4; ++b) {
                    const int q = grp * 4 + b;
                    float zi, zf, zg, zo;
                    unpack2(zif[grp][b], zi, zf);
                    unpack2(zgo[grp][b], zg, zo);
                    cs[q] = fmaf(sig_h(zf), cs[q], sig_h(zi) * tanhap(zg));
                    hs[q] = sig_h(zo) * tanhap(cs[q]);
                }
                // store duplicated h (conflict-free STS.128)
                *(float4*)(hbuf[grp][0] + nxt * 64 + lane * 2) =
                    make_float4(hs[grp*4+0], hs[grp*4+0], hs[grp*4+1], hs[grp*4+1]);
                *(float4*)(hbuf[grp][1] + nxt * 64 + lane * 2) =
                    make_float4(hs[grp*4+2], hs[grp*4+2], hs[grp*4+3], hs[grp*4+3]);
            }
            cur = nxt;
            __syncwarp();
        }
        __syncwarp();
    }

    // ---- output head: out[q] = sum_j h[q][j]*W_out[j] + b_out ----
    const float wo = W_out[lane];
    float v[8];
#pragma unroll
    for (int q = 0; q < 8; ++q) v[q] = hs[q] * wo;
#pragma unroll
    for (int off = 16; off; off >>= 1) {
#pragma unroll
        for (int q = 0; q < 8; ++q)
            v[q] += __shfl_xor_sync(0xffffffffu, v[q], off);
    }
    if (lane == 0) {
        const float bout = b_out[0];
        const int bb = blockIdx.x * 8;
#pragma unroll
        for (int q = 0; q < 8; ++q) out[bb + q] = v[q] + bout;
    }
}

extern "C" void kernel_launch(void* const* d_in, const int* in_sizes, int n_in,
                              void* d_out, int out_size)
{
    const float* x     = (const float*)d_in[0];
    const float* W_ih  = (const float*)d_in[1];
    const float* W_hh  = (const float*)d_in[2];
    const float* b_ih  = (const float*)d_in[3];
    const float* b_hh  = (const float*)d_in[4];
    const float* W_out = (const float*)d_in[5];
    const float* b_out = (const float*)d_in[6];
    float* out = (float*)d_out;

    lstm_kernel<<<B_TOT / 8, 32>>>(x, W_ih, W_hh, b_ih, b_hh, W_out, b_out, out);
}